// round 12
// baseline (speedup 1.0000x reference)
#include <cuda_runtime.h>
#include <cstdint>

// ============================================================================
// Problem constants
// ============================================================================
#define MDIM   65536      // B*N = 2048*32
#define KDIM   1024       // model dim
#define NQKV   3072       // 3*DIM
#define NPROJ  1024
#define HEADS  16
#define HEAD_D 64
#define SEQ    32
#define BATCH  2048
#define KT     32         // k-tiles of 32 per K=1024

// ============================================================================
// Scratch (allocation-free rule: __device__ globals)
// ============================================================================
__device__ __align__(256) float g_qkv  [(size_t)MDIM * NQKV];   // 805 MB, fp32 row-major
__device__ __align__(256) float g_xs   [(size_t)MDIM * KDIM];   // 256 MB, tf32 tiled
__device__ __align__(256) float g_attns[(size_t)MDIM * KDIM];   // 256 MB, tf32 tiled
__device__ __align__(256) float g_wqs  [(size_t)NQKV * KDIM];   //  12 MB, tf32 tiled
__device__ __align__(256) float g_wps  [(size_t)NPROJ * KDIM];  //   4 MB, tf32 tiled

// ============================================================================
// Helpers — BASELINE PTX ONLY (compute_103 target: no tcgen05/TMEM)
// ============================================================================

// fp32 -> tf32 round-to-nearest (RNA). Unbiased rounding is correctness-
// critical: truncation bias over K=1024 would give ~1e-2 rel_err.
__device__ __forceinline__ float f2tf32(float x) {
    uint32_t y;
    asm("cvt.rna.tf32.f32 %0, %1;" : "=r"(y) : "f"(x));
    return __uint_as_float(y);
}

// m16n8k8 tf32 HMMA (sm_80 baseline instruction), measured rt_SMSP ~= 4
__device__ __forceinline__ void mma_tf32(float& c0, float& c1, float& c2, float& c3,
                                         float a0, float a1, float a2, float a3,
                                         float b0, float b1) {
    asm volatile(
        "mma.sync.aligned.m16n8k8.row.col.f32.tf32.tf32.f32 "
        "{%0,%1,%2,%3}, {%4,%5,%6,%7}, {%8,%9}, {%0,%1,%2,%3};"
        : "+f"(c0), "+f"(c1), "+f"(c2), "+f"(c3)
        : "r"(__float_as_uint(a0)), "r"(__float_as_uint(a1)),
          "r"(__float_as_uint(a2)), "r"(__float_as_uint(a3)),
          "r"(__float_as_uint(b0)), "r"(__float_as_uint(b1)));
}

// ----------------------------------------------------------------------------
// Tiled scratch layout (single source of truth):
//   matrix [R rows][K cols] -> tiles of 128 rows x 32 cols, 16 KB each,
//   tile id = (row>>7)*KT + (col>>5).
//   Within tile: r = row&127; c = col&31; ks = c>>3; j = c&7.
//   Physical float col p = ks*8 + 2*(j&3) + (j>>2)   (pairs (k,k+4) -> LDS.64)
//   Byte offset = r*128 + ((p<<2) ^ ((r&7)<<4))      (XOR swizzle pre-applied)
// ----------------------------------------------------------------------------
__device__ __forceinline__ size_t tiled_byte(int row, int col, int /*K*/) {
    int kt = col >> 5, c = col & 31;
    int ks = c >> 3, j = c & 7;
    int p  = ks * 8 + 2 * (j & 3) + (j >> 2);
    size_t tile = ((size_t)(row >> 7) * KT + kt) << 14;
    return tile + (size_t)((row & 127) << 7) + (uint32_t)(((p << 2)) ^ ((row & 7) << 4));
}

// ============================================================================
// Pre-pass: fp32 row-major -> tf32 tiled/permuted/swizzled scratch
// ============================================================================
__global__ void __launch_bounds__(256)
convert_tile_kernel(const float* __restrict__ src, float* __restrict__ dst,
                    int R, int K)
{
    size_t gid = (size_t)blockIdx.x * 256 + threadIdx.x;
    size_t total = ((size_t)R * K) >> 2;
    if (gid >= total) return;
    int kq  = K >> 2;
    int row = (int)(gid / kq);
    int c4  = (int)(gid % kq) << 2;
    float4 v = *(const float4*)(src + (size_t)row * K + c4);
    char* base = (char*)dst;
    float e[4] = {v.x, v.y, v.z, v.w};
#pragma unroll
    for (int i = 0; i < 4; ++i)
        *(float*)(base + tiled_byte(row, c4 + i, K)) = f2tf32(e[i]);
}

// ============================================================================
// GEMM: C[M,N] = At[M,K] @ Bt[N,K]^T + bias   (inputs pre-tiled tf32)
//   CTA tile 128x128, 4 warps (2x2) of 64x64 warp tiles -> 128 B LDS per MMA
//   (crossbar demand ~1500 cyc/kt-SM incl. cp.async — BELOW tensor floor).
//   Double-buffered fragment registers pipeline ks+1 loads under ks MMAs.
//   NO register cap: __launch_bounds__(128) alone -> ptxas max 255 regs,
//   2 CTAs x 128 thr x 255 = 65280 <= 65536 RF, smem (96 KB) still packs
//   2 CTAs/SM. (Round-7's (128,2) clamp caused the spills that broke this
//   exact config — L2=51% signature.)
// ============================================================================
static constexpr int STAGES = 3;
static constexpr int STAGE_BYTES = 32768;               // A 16KB + B 16KB
static constexpr int GEMM_SMEM = STAGES * STAGE_BYTES;  // 96 KB -> 2 CTAs/SM

__global__ void __launch_bounds__(128)
gemm_tc_kernel(const float* __restrict__ At, const float* __restrict__ Bt,
               const float* __restrict__ bias, float* __restrict__ C,
               int M, int N)
{
    extern __shared__ char smem[];
    uint32_t sb;
    asm("{ .reg .u64 t; cvta.to.shared.u64 t, %1; cvt.u32.u64 %0, t; }"
        : "=r"(sb) : "l"(smem));

    const int tid  = threadIdx.x;
    const int lane = tid & 31;
    const int w    = tid >> 5;
    const int wm   = w >> 1;     // 0..1  (64-row half)
    const int wn   = w & 1;      // 0..1  (64-col half)
    const int lg   = lane >> 2;  // 0..7
    const int lc   = lane & 3;   // 0..3

    // ---- grid swizzle: groups of 16 M-tiles, N-tile outer within group ----
    const int tiles_n = N >> 7;
    const int per = 16 * tiles_n;
    const int grp = blockIdx.x / per;
    const int r_  = blockIdx.x % per;
    const int mtile = grp * 16 + (r_ % 16);
    const int ntile = r_ / 16;
    const int m0 = mtile << 7, n0 = ntile << 7;

    // ---- producer: identity-copy one 16KB A tile + one 16KB B tile ----
    const char* Abase = (const char*)At + (((size_t)mtile * KT) << 14);
    const char* Bbase = (const char*)Bt + (((size_t)ntile * KT) << 14);
    const int cpo = tid * 128;  // 128 threads x 128 B = 16 KB per region

    auto issue = [&](int kt, int s) {
        const char* asrc = Abase + ((size_t)kt << 14) + cpo;
        const char* bsrc = Bbase + ((size_t)kt << 14) + cpo;
        uint32_t ad = sb + s * STAGE_BYTES + cpo;
        uint32_t bd = ad + 16384;
#pragma unroll
        for (int j = 0; j < 8; ++j) {
            asm volatile("cp.async.cg.shared.global [%0], [%1], 16;"
                         :: "r"(ad + j * 16), "l"(asrc + j * 16));
            asm volatile("cp.async.cg.shared.global [%0], [%1], 16;"
                         :: "r"(bd + j * 16), "l"(bsrc + j * 16));
        }
        asm volatile("cp.async.commit_group;" ::: "memory");
    };

    // ---- consumer addresses ----
    // frag pair (k, k+4) byte: r*128 + [(8*lc) ^ ((lg&1)<<4)] + [(ks ^ (lg>>1))<<5]
    const uint32_t lo = (uint32_t)((8 * lc) ^ ((lg & 1) << 4));
    uint32_t sks[4];
#pragma unroll
    for (int ks = 0; ks < 4; ++ks) sks[ks] = (uint32_t)((ks ^ (lg >> 1)) << 5);
    uint32_t baseA[4], baseB[8];
#pragma unroll
    for (int mt = 0; mt < 4; ++mt)
        baseA[mt] = (uint32_t)((wm * 64 + mt * 16 + lg) << 7) + lo;
#pragma unroll
    for (int nt = 0; nt < 8; ++nt)
        baseB[nt] = (uint32_t)((wn * 64 + nt * 8 + lg) << 7) + 16384u + lo;

    float acc[4][8][4];
#pragma unroll
    for (int mt = 0; mt < 4; ++mt)
#pragma unroll
        for (int nt = 0; nt < 8; ++nt)
#pragma unroll
            for (int i = 0; i < 4; ++i) acc[mt][nt][i] = 0.f;

    // double-buffered fragment registers (the point of this round:
    // with 255 regs available these STAY in registers)
    float2 a0[2][4], a1[2][4], fb[2][8];

    auto ldfrag = [&](int buf, int ks, uint32_t sg) {
#pragma unroll
        for (int mt = 0; mt < 4; ++mt) {
            uint32_t ad = sg + baseA[mt] + sks[ks];
            asm("ld.shared.v2.f32 {%0,%1}, [%2];"
                : "=f"(a0[buf][mt].x), "=f"(a0[buf][mt].y) : "r"(ad));
            asm("ld.shared.v2.f32 {%0,%1}, [%2+1024];"       // row +8
                : "=f"(a1[buf][mt].x), "=f"(a1[buf][mt].y) : "r"(ad));
        }
#pragma unroll
        for (int nt = 0; nt < 8; ++nt) {
            uint32_t bd = sg + baseB[nt] + sks[ks];
            asm("ld.shared.v2.f32 {%0,%1}, [%2];"
                : "=f"(fb[buf][nt].x), "=f"(fb[buf][nt].y) : "r"(bd));
        }
    };

    issue(0, 0);
    issue(1, 1);

#pragma unroll 1
    for (int kt = 0; kt < KT; ++kt) {
        const int s = kt % 3;
        if (kt + 1 < KT) asm volatile("cp.async.wait_group 1;" ::: "memory");
        else             asm volatile("cp.async.wait_group 0;" ::: "memory");
        __syncthreads();
        if (kt + 2 < KT) issue(kt + 2, (kt + 2) % 3);

        const uint32_t sg = sb + (uint32_t)(s * STAGE_BYTES);
        ldfrag(0, 0, sg);
#pragma unroll
        for (int ks = 0; ks < 4; ++ks) {
            const int cur = ks & 1;
            if (ks < 3) ldfrag(cur ^ 1, ks + 1, sg);   // overlap LDS with MMAs
#pragma unroll
            for (int mt = 0; mt < 4; ++mt)
#pragma unroll
                for (int nt = 0; nt < 8; ++nt)
                    mma_tf32(acc[mt][nt][0], acc[mt][nt][1],
                             acc[mt][nt][2], acc[mt][nt][3],
                             a0[cur][mt].x, a1[cur][mt].x,
                             a0[cur][mt].y, a1[cur][mt].y,
                             fb[cur][nt].x, fb[cur][nt].y);
        }
    }

    // ---- epilogue: direct float2 global stores with bias ----
#pragma unroll
    for (int nt = 0; nt < 8; ++nt) {
        const int col = n0 + wn * 64 + nt * 8 + 2 * lc;
        const float b0 = __ldg(bias + col), b1 = __ldg(bias + col + 1);
#pragma unroll
        for (int mt = 0; mt < 4; ++mt) {
            const int row = m0 + wm * 64 + mt * 16 + lg;
            float2 v0 = make_float2(acc[mt][nt][0] + b0, acc[mt][nt][1] + b1);
            float2 v1 = make_float2(acc[mt][nt][2] + b0, acc[mt][nt][3] + b1);
            *(float2*)(C + (size_t)row * N + col)       = v0;
            *(float2*)(C + (size_t)(row + 8) * N + col) = v1;
        }
    }
}

// ============================================================================
// Attention: per (b,h): s = q k^T * 0.125 + rel_bias[h]; p = softmax; o = p v
// Output written directly as tf32 tiled scratch (free conversion for GEMM2).
// ============================================================================
__global__ void __launch_bounds__(128)
attn_kernel(const float* __restrict__ qkv, const float* __restrict__ rel_bias,
            float* __restrict__ attn_ts)
{
    __shared__ float q[32][65], k[32][65], v[32][65], s[32][33];
    const int bh = blockIdx.x;
    const int b = bh >> 4, h = bh & 15;
    const int tid = threadIdx.x;

    const size_t base = (size_t)b * SEQ * NQKV + (size_t)h * HEAD_D;
    for (int i = tid; i < SEQ * HEAD_D; i += 128) {
        int n = i >> 6, d = i & 63;
        size_t a = base + (size_t)n * NQKV + d;
        q[n][d] = qkv[a];
        k[n][d] = qkv[a + 1024];
        v[n][d] = qkv[a + 2048];
    }
    __syncthreads();

    {
        const int n  = tid >> 2;
        const int mb = tid & 3;
        const float* rbp = rel_bias + ((size_t)h * 32 + n) * 32;
#pragma unroll
        for (int j = 0; j < 8; ++j) {
            int m = mb + 4 * j;
            float acc = 0.f;
#pragma unroll
            for (int d = 0; d < 64; ++d) acc += q[n][d] * k[m][d];
            s[n][m] = acc * 0.125f + rbp[m];
        }
    }
    __syncthreads();

    {
        const int lane = tid & 31, w = tid >> 5;
        for (int rr = w * 8; rr < w * 8 + 8; ++rr) {
            float x = s[rr][lane];
            float mx = x;
#pragma unroll
            for (int off = 16; off > 0; off >>= 1)
                mx = fmaxf(mx, __shfl_xor_sync(0xFFFFFFFFu, mx, off));
            float e = __expf(x - mx);
            float sum = e;
#pragma unroll
            for (int off = 16; off > 0; off >>= 1)
                sum += __shfl_xor_sync(0xFFFFFFFFu, sum, off);
            s[rr][lane] = e / sum;
        }
    }
    __syncthreads();

    // out = p @ v, stored tf32-tiled at (row = b*32+n, col = h*64+d)
    char* base_ts = (char*)attn_ts;
    for (int i = tid; i < SEQ * HEAD_D; i += 128) {
        int n = i >> 6, d = i & 63;
        float acc = 0.f;
#pragma unroll
        for (int m = 0; m < 32; ++m) acc += s[n][m] * v[m][d];
        int row = b * SEQ + n;
        int col = h * HEAD_D + d;
        *(float*)(base_ts + tiled_byte(row, col, KDIM)) = f2tf32(acc);
    }
}

// ============================================================================
// Launcher
// ============================================================================
extern "C" void kernel_launch(void* const* d_in, const int* in_sizes, int n_in,
                              void* d_out, int out_size)
{
    const float* x      = (const float*)d_in[0];
    const float* W_qkv  = (const float*)d_in[1];
    const float* b_qkv  = (const float*)d_in[2];
    const float* W_proj = (const float*)d_in[3];
    const float* b_proj = (const float*)d_in[4];
    const float* rbias  = (const float*)d_in[5];
    float* out = (float*)d_out;

    void *p_qkv = nullptr, *p_xs = nullptr, *p_attns = nullptr,
         *p_wqs = nullptr, *p_wps = nullptr;
    cudaGetSymbolAddress(&p_qkv,   g_qkv);
    cudaGetSymbolAddress(&p_xs,    g_xs);
    cudaGetSymbolAddress(&p_attns, g_attns);
    cudaGetSymbolAddress(&p_wqs,   g_wqs);
    cudaGetSymbolAddress(&p_wps,   g_wps);

    cudaFuncSetAttribute(gemm_tc_kernel,
                         cudaFuncAttributeMaxDynamicSharedMemorySize, GEMM_SMEM);

    // Pre-pass: convert + tile (x, W_qkv, W_proj)
    convert_tile_kernel<<<((size_t)MDIM * KDIM / 4 + 255) / 256, 256>>>(
        x, (float*)p_xs, MDIM, KDIM);
    convert_tile_kernel<<<((size_t)NQKV * KDIM / 4 + 255) / 256, 256>>>(
        W_qkv, (float*)p_wqs, NQKV, KDIM);
    convert_tile_kernel<<<((size_t)NPROJ * KDIM / 4 + 255) / 256, 256>>>(
        W_proj, (float*)p_wps, NPROJ, KDIM);

    // GEMM1: qkv = x @ W_qkv^T + b_qkv  [65536 x 3072]
    gemm_tc_kernel<<<(MDIM / 128) * (NQKV / 128), 128, GEMM_SMEM>>>(
        (const float*)p_xs, (const float*)p_wqs, b_qkv, (float*)p_qkv, MDIM, NQKV);

    // Attention: 2048*16 (b,h) blocks -> tf32 tiled scratch
    attn_kernel<<<BATCH * HEADS, 128>>>(
        (const float*)p_qkv, rbias, (float*)p_attns);

    // GEMM2: out = attn @ W_proj^T + b_proj  [65536 x 1024]
    gemm_tc_kernel<<<(MDIM / 128) * (NPROJ / 128), 128, GEMM_SMEM>>>(
        (const float*)p_attns, (const float*)p_wps, b_proj, out, MDIM, NPROJ);
}

// round 14
// speedup vs baseline: 2.4740x; 2.4740x over previous
#include <cuda_runtime.h>
#include <cuda_fp16.h>
#include <cstdint>

// ============================================================================
// Problem constants
// ============================================================================
#define MDIM   65536      // B*N = 2048*32
#define KDIM   1024       // model dim
#define NQKV   3072       // 3*DIM
#define NPROJ  1024
#define HEADS  16
#define HEAD_D 64
#define SEQ    32
#define BATCH  2048
#define KT     32         // k-tiles of 32 per K=1024

// fp16 tiled layout: tile = 128 rows x 32 k-halfs = 64 B/row, pitch 64, 8 KB
static constexpr int TILE16 = 8192;

// ============================================================================
// Scratch (allocation-free rule: __device__ globals)
// ============================================================================
__device__ __align__(256) float g_qkv[(size_t)MDIM * NQKV];              // 805 MB fp32
__device__ __align__(256) unsigned char g_xs16 [(size_t)(MDIM/128) * KT * TILE16]; // 134 MB
__device__ __align__(256) unsigned char g_at16 [(size_t)(MDIM/128) * KT * TILE16]; // 134 MB
__device__ __align__(256) unsigned char g_wq16 [(size_t)(NQKV/128) * KT * TILE16]; //   6 MB
__device__ __align__(256) unsigned char g_wp16 [(size_t)(NPROJ/128) * KT * TILE16];//   2 MB

// ============================================================================
// Helpers — BASELINE PTX ONLY (compute_103 target)
// ============================================================================

// m16n8k16 fp16 HMMA, fp32 accumulate. Same 10-bit mantissa as tf32 ->
// same rounding error as the measured 5.59e-4, at 2x MACs/instr, half bytes.
__device__ __forceinline__ void mma_f16(float& c0, float& c1, float& c2, float& c3,
                                        uint32_t a0, uint32_t a1, uint32_t a2, uint32_t a3,
                                        uint32_t b0, uint32_t b1) {
    asm volatile(
        "mma.sync.aligned.m16n8k16.row.col.f32.f16.f16.f32 "
        "{%0,%1,%2,%3}, {%4,%5,%6,%7}, {%8,%9}, {%0,%1,%2,%3};"
        : "+f"(c0), "+f"(c1), "+f"(c2), "+f"(c3)
        : "r"(a0), "r"(a1), "r"(a2), "r"(a3), "r"(b0), "r"(b1));
}

// ----------------------------------------------------------------------------
// fp16 tiled layout (single source of truth):
//   [R rows][K cols] -> tiles 128 rows x 32 k-halfs (64 B/row, 8 KB/tile),
//   tile id = (row>>7)*KT + (col>>5).
//   Row layout: slot lc (16 B, lc=0..3) = halfs
//     [2lc, 2lc+1, 2lc+8, 2lc+9 | 16+2lc, 17+2lc, 24+2lc, 25+2lc]
//   -> one LDS.128 at (row, lc) yields {a0,a2} (or {b0,b1}) for BOTH k16
//   steps of the kt. Quarter-warp phases (lg in {r,r+1} x lc) hit slots
//   lg*4+lc = 8 distinct 16B slots -> conflict-free at pitch 64, 16B-aligned.
// ----------------------------------------------------------------------------
__device__ __forceinline__ size_t tiled16_byte(int row, int col) {
    int kt = col >> 5, c = col & 31;
    int ks = (c >> 4) & 1;
    int j  = c & 15;
    int lc = (j & 7) >> 1;
    int p  = ((j >> 3) << 1) | (c & 1);
    size_t tile = ((size_t)(row >> 7) * KT + kt) * (size_t)TILE16;
    return tile + (size_t)((row & 127) << 6) + lc * 16 + ks * 8 + p * 2;
}

// ============================================================================
// Pre-pass: fp32 row-major -> fp16 (RN) tiled scratch
// ============================================================================
__global__ void __launch_bounds__(256)
convert_tile16_kernel(const float* __restrict__ src, unsigned char* __restrict__ dst,
                      int R, int K)
{
    size_t gid = (size_t)blockIdx.x * 256 + threadIdx.x;
    size_t total = ((size_t)R * K) >> 2;
    if (gid >= total) return;
    int kq  = K >> 2;
    int row = (int)(gid / kq);
    int c4  = (int)(gid % kq) << 2;
    float4 v = *(const float4*)(src + (size_t)row * K + c4);
    __half2 h0 = __floats2half2_rn(v.x, v.y);
    __half2 h1 = __floats2half2_rn(v.z, v.w);
    *(__half2*)(dst + tiled16_byte(row, c4))     = h0;  // cols c4, c4+1 adjacent
    *(__half2*)(dst + tiled16_byte(row, c4 + 2)) = h1;  // cols c4+2, c4+3
}

// ============================================================================
// GEMM: C[M,N] = At[M,K] @ Bt[N,K]^T + bias   (inputs pre-tiled fp16)
//   CTA 128x128, 8 warps (2x4) of 64x32 tiles. 3-stage cp.async + syncthreads
//   (proven R6 pipeline). Per warp-kt: 12 conflict-free LDS.128 + 32 MMAs
//   (fp16 halves crossbar bytes AND MMA count vs tf32).
// ============================================================================
static constexpr int STAGES = 3;
static constexpr int STAGE_BYTES = 2 * TILE16;          // A 8K + B 8K
static constexpr int GEMM_SMEM = STAGES * STAGE_BYTES;  // 48 KB -> 2 CTAs/SM easily

__global__ void __launch_bounds__(256, 2)
gemm_f16_kernel(const unsigned char* __restrict__ At, const unsigned char* __restrict__ Bt,
                const float* __restrict__ bias, float* __restrict__ C,
                int M, int N)
{
    extern __shared__ char smem[];
    uint32_t sb;
    asm("{ .reg .u64 t; cvta.to.shared.u64 t, %1; cvt.u32.u64 %0, t; }"
        : "=r"(sb) : "l"(smem));

    const int tid  = threadIdx.x;
    const int lane = tid & 31;
    const int w    = tid >> 5;
    const int wm   = w >> 2;     // 0..1  (64-row half)
    const int wn   = w & 3;      // 0..3  (32-col band)
    const int lg   = lane >> 2;  // 0..7
    const int lc   = lane & 3;   // 0..3

    // ---- grid swizzle: groups of 16 M-tiles, N-tile outer within group ----
    const int tiles_n = N >> 7;
    const int per = 16 * tiles_n;
    const int grp = blockIdx.x / per;
    const int r_  = blockIdx.x % per;
    const int mtile = grp * 16 + (r_ % 16);
    const int ntile = r_ / 16;
    const int m0 = mtile << 7, n0 = ntile << 7;

    // ---- producer: identity-copy one 8KB A tile + one 8KB B tile ----
    const unsigned char* Abase = At + (size_t)mtile * KT * TILE16;
    const unsigned char* Bbase = Bt + (size_t)ntile * KT * TILE16;
    const int o0 = tid * 16;            // 512 chunks of 16B: t and t+256
    const int o1 = (tid + 256) * 16;

    auto issue = [&](int kt, int s) {
        const unsigned char* asrc = Abase + (size_t)kt * TILE16;
        const unsigned char* bsrc = Bbase + (size_t)kt * TILE16;
        uint32_t ad = sb + s * STAGE_BYTES;
        uint32_t bd = ad + TILE16;
        asm volatile("cp.async.cg.shared.global [%0], [%1], 16;"
                     :: "r"(ad + o0), "l"(asrc + o0));
        asm volatile("cp.async.cg.shared.global [%0], [%1], 16;"
                     :: "r"(bd + o0), "l"(bsrc + o0));
        asm volatile("cp.async.cg.shared.global [%0], [%1], 16;"
                     :: "r"(ad + o1), "l"(asrc + o1));
        asm volatile("cp.async.cg.shared.global [%0], [%1], 16;"
                     :: "r"(bd + o1), "l"(bsrc + o1));
        asm volatile("cp.async.commit_group;" ::: "memory");
    };

    // ---- consumer addresses: (row)*64 + lc*16, A rows = wm*64+mt*16+lg ----
    uint32_t baseA[4], baseB[4];
#pragma unroll
    for (int mt = 0; mt < 4; ++mt)
        baseA[mt] = (uint32_t)((wm * 64 + mt * 16 + lg) << 6) + (uint32_t)(lc * 16);
#pragma unroll
    for (int nt = 0; nt < 4; ++nt)
        baseB[nt] = (uint32_t)TILE16 + (uint32_t)((wn * 32 + nt * 8 + lg) << 6)
                  + (uint32_t)(lc * 16);

    float acc[4][4][4];
#pragma unroll
    for (int mt = 0; mt < 4; ++mt)
#pragma unroll
        for (int nt = 0; nt < 4; ++nt)
#pragma unroll
            for (int i = 0; i < 4; ++i) acc[mt][nt][i] = 0.f;

    issue(0, 0);
    issue(1, 1);

#pragma unroll 1
    for (int kt = 0; kt < KT; ++kt) {
        const int s = kt % 3;
        if (kt + 1 < KT) asm volatile("cp.async.wait_group 1;" ::: "memory");
        else             asm volatile("cp.async.wait_group 0;" ::: "memory");
        __syncthreads();
        if (kt + 2 < KT) issue(kt + 2, (kt + 2) % 3);

        const uint32_t sg = sb + (uint32_t)(s * STAGE_BYTES);

        // A fragments: one LDS.128 per (mt, row half) covers both k16 steps.
        // av[mt][h][0..3]: v0=a0(ks0) v1=a2(ks0) v2=a0(ks1) v3=a2(ks1)
        uint32_t av[4][2][4];
#pragma unroll
        for (int mt = 0; mt < 4; ++mt) {
            uint32_t ad = sg + baseA[mt];
            asm("ld.shared.v4.b32 {%0,%1,%2,%3}, [%4];"
                : "=r"(av[mt][0][0]), "=r"(av[mt][0][1]),
                  "=r"(av[mt][0][2]), "=r"(av[mt][0][3]) : "r"(ad));
            asm("ld.shared.v4.b32 {%0,%1,%2,%3}, [%4+512];"      // row +8
                : "=r"(av[mt][1][0]), "=r"(av[mt][1][1]),
                  "=r"(av[mt][1][2]), "=r"(av[mt][1][3]) : "r"(ad));
        }
#pragma unroll
        for (int nt = 0; nt < 4; ++nt) {
            uint32_t bv[4];   // v0=b0(ks0) v1=b1(ks0) v2=b0(ks1) v3=b1(ks1)
            uint32_t bd = sg + baseB[nt];
            asm("ld.shared.v4.b32 {%0,%1,%2,%3}, [%4];"
                : "=r"(bv[0]), "=r"(bv[1]), "=r"(bv[2]), "=r"(bv[3]) : "r"(bd));
#pragma unroll
            for (int mt = 0; mt < 4; ++mt) {
                // ks0:  a0,a1,a2,a3 = rowlg.v0, rowlg8.v0, rowlg.v1, rowlg8.v1
                mma_f16(acc[mt][nt][0], acc[mt][nt][1], acc[mt][nt][2], acc[mt][nt][3],
                        av[mt][0][0], av[mt][1][0], av[mt][0][1], av[mt][1][1],
                        bv[0], bv[1]);
                // ks1
                mma_f16(acc[mt][nt][0], acc[mt][nt][1], acc[mt][nt][2], acc[mt][nt][3],
                        av[mt][0][2], av[mt][1][2], av[mt][0][3], av[mt][1][3],
                        bv[2], bv[3]);
            }
        }
    }

    // ---- epilogue: direct float2 global stores with bias ----
#pragma unroll
    for (int nt = 0; nt < 4; ++nt) {
        const int col = n0 + wn * 32 + nt * 8 + 2 * lc;
        const float b0 = __ldg(bias + col), b1 = __ldg(bias + col + 1);
#pragma unroll
        for (int mt = 0; mt < 4; ++mt) {
            const int row = m0 + wm * 64 + mt * 16 + lg;
            float2 v0 = make_float2(acc[mt][nt][0] + b0, acc[mt][nt][1] + b1);
            float2 v1 = make_float2(acc[mt][nt][2] + b0, acc[mt][nt][3] + b1);
            *(float2*)(C + (size_t)row * N + col)       = v0;
            *(float2*)(C + (size_t)(row + 8) * N + col) = v1;
        }
    }
}

// ============================================================================
// Attention: per (b,h): s = q k^T * 0.125 + rel_bias[h]; p = softmax; o = p v
// qkv read fp32 (keeps softmax inputs exact); output written fp16-tiled.
// ============================================================================
__global__ void __launch_bounds__(128)
attn_kernel(const float* __restrict__ qkv, const float* __restrict__ rel_bias,
            unsigned char* __restrict__ attn_ts)
{
    __shared__ float q[32][65], k[32][65], v[32][65], s[32][33];
    const int bh = blockIdx.x;
    const int b = bh >> 4, h = bh & 15;
    const int tid = threadIdx.x;

    const size_t base = (size_t)b * SEQ * NQKV + (size_t)h * HEAD_D;
    for (int i = tid; i < SEQ * HEAD_D; i += 128) {
        int n = i >> 6, d = i & 63;
        size_t a = base + (size_t)n * NQKV + d;
        q[n][d] = qkv[a];
        k[n][d] = qkv[a + 1024];
        v[n][d] = qkv[a + 2048];
    }
    __syncthreads();

    {
        const int n  = tid >> 2;
        const int mb = tid & 3;
        const float* rbp = rel_bias + ((size_t)h * 32 + n) * 32;
#pragma unroll
        for (int j = 0; j < 8; ++j) {
            int m = mb + 4 * j;
            float acc = 0.f;
#pragma unroll
            for (int d = 0; d < 64; ++d) acc += q[n][d] * k[m][d];
            s[n][m] = acc * 0.125f + rbp[m];
        }
    }
    __syncthreads();

    {
        const int lane = tid & 31, w = tid >> 5;
        for (int rr = w * 8; rr < w * 8 + 8; ++rr) {
            float x = s[rr][lane];
            float mx = x;
#pragma unroll
            for (int off = 16; off > 0; off >>= 1)
                mx = fmaxf(mx, __shfl_xor_sync(0xFFFFFFFFu, mx, off));
            float e = __expf(x - mx);
            float sum = e;
#pragma unroll
            for (int off = 16; off > 0; off >>= 1)
                sum += __shfl_xor_sync(0xFFFFFFFFu, sum, off);
            s[rr][lane] = e / sum;
        }
    }
    __syncthreads();

    // out = p @ v -> fp16 tiled (row = b*32+n, col = h*64+d), pairs of d
    for (int i = tid; i < SEQ * HEAD_D / 2; i += 128) {
        int n = i >> 5, d2 = (i & 31) << 1;
        float acc0 = 0.f, acc1 = 0.f;
#pragma unroll
        for (int m = 0; m < 32; ++m) {
            float p = s[n][m];
            acc0 += p * v[m][d2];
            acc1 += p * v[m][d2 + 1];
        }
        int row = b * SEQ + n;
        int col = h * HEAD_D + d2;
        *(__half2*)(attn_ts + tiled16_byte(row, col)) = __floats2half2_rn(acc0, acc1);
    }
}

// ============================================================================
// Launcher
// ============================================================================
extern "C" void kernel_launch(void* const* d_in, const int* in_sizes, int n_in,
                              void* d_out, int out_size)
{
    const float* x      = (const float*)d_in[0];
    const float* W_qkv  = (const float*)d_in[1];
    const float* b_qkv  = (const float*)d_in[2];
    const float* W_proj = (const float*)d_in[3];
    const float* b_proj = (const float*)d_in[4];
    const float* rbias  = (const float*)d_in[5];
    float* out = (float*)d_out;

    void *p_qkv = nullptr, *p_xs = nullptr, *p_at = nullptr,
         *p_wq = nullptr, *p_wp = nullptr;
    cudaGetSymbolAddress(&p_qkv, g_qkv);
    cudaGetSymbolAddress(&p_xs,  g_xs16);
    cudaGetSymbolAddress(&p_at,  g_at16);
    cudaGetSymbolAddress(&p_wq,  g_wq16);
    cudaGetSymbolAddress(&p_wp,  g_wp16);

    cudaFuncSetAttribute(gemm_f16_kernel,
                         cudaFuncAttributeMaxDynamicSharedMemorySize, GEMM_SMEM);

    // Pre-pass: convert + tile (x, W_qkv, W_proj) to fp16
    convert_tile16_kernel<<<((size_t)MDIM * KDIM / 4 + 255) / 256, 256>>>(
        x, (unsigned char*)p_xs, MDIM, KDIM);
    convert_tile16_kernel<<<((size_t)NQKV * KDIM / 4 + 255) / 256, 256>>>(
        W_qkv, (unsigned char*)p_wq, NQKV, KDIM);
    convert_tile16_kernel<<<((size_t)NPROJ * KDIM / 4 + 255) / 256, 256>>>(
        W_proj, (unsigned char*)p_wp, NPROJ, KDIM);

    // GEMM1: qkv = x @ W_qkv^T + b_qkv  [65536 x 3072] (fp32 out)
    gemm_f16_kernel<<<(MDIM / 128) * (NQKV / 128), 256, GEMM_SMEM>>>(
        (const unsigned char*)p_xs, (const unsigned char*)p_wq, b_qkv,
        (float*)p_qkv, MDIM, NQKV);

    // Attention: 2048*16 (b,h) blocks -> fp16 tiled scratch
    attn_kernel<<<BATCH * HEADS, 128>>>(
        (const float*)p_qkv, rbias, (unsigned char*)p_at);

    // GEMM2: out = attn @ W_proj^T + b_proj  [65536 x 1024]
    gemm_f16_kernel<<<(MDIM / 128) * (NPROJ / 128), 256, GEMM_SMEM>>>(
        (const unsigned char*)p_at, (const unsigned char*)p_wp, b_proj,
        out, MDIM, NPROJ);
}

// round 15
// speedup vs baseline: 2.8118x; 1.1366x over previous
#include <cuda_runtime.h>
#include <cuda_fp16.h>
#include <cstdint>

// ============================================================================
// Problem constants
// ============================================================================
#define MDIM   65536      // B*N = 2048*32
#define KDIM   1024       // model dim
#define NQKV   3072       // 3*DIM
#define NPROJ  1024
#define HEADS  16
#define HEAD_D 64
#define SEQ    32
#define BATCH  2048
#define KT     32         // k-tiles of 32 per K=1024

// fp16 tiled layout: tile = 128 rows x 32 k-halfs = 64 B/row, pitch 64, 8 KB
static constexpr int TILE16 = 8192;

// ============================================================================
// Scratch (allocation-free rule: __device__ globals)
// ============================================================================
__device__ __align__(256) float g_qkv[(size_t)MDIM * NQKV];              // 805 MB fp32
__device__ __align__(256) unsigned char g_xs16 [(size_t)(MDIM/128) * KT * TILE16]; // 134 MB
__device__ __align__(256) unsigned char g_at16 [(size_t)(MDIM/128) * KT * TILE16]; // 134 MB
__device__ __align__(256) unsigned char g_wq16 [(size_t)(NQKV/128) * KT * TILE16]; //   6 MB
__device__ __align__(256) unsigned char g_wp16 [(size_t)(NPROJ/128) * KT * TILE16];//   2 MB

// ============================================================================
// Helpers — BASELINE PTX ONLY (compute_103 target)
// ============================================================================

// m16n8k16 fp16 HMMA, fp32 accumulate (same 10-bit mantissa as tf32;
// measured rel_err identical at half the bytes and half the MMA count).
__device__ __forceinline__ void mma_f16(float& c0, float& c1, float& c2, float& c3,
                                        uint32_t a0, uint32_t a1, uint32_t a2, uint32_t a3,
                                        uint32_t b0, uint32_t b1) {
    asm volatile(
        "mma.sync.aligned.m16n8k16.row.col.f32.f16.f16.f32 "
        "{%0,%1,%2,%3}, {%4,%5,%6,%7}, {%8,%9}, {%0,%1,%2,%3};"
        : "+f"(c0), "+f"(c1), "+f"(c2), "+f"(c3)
        : "r"(a0), "r"(a1), "r"(a2), "r"(a3), "r"(b0), "r"(b1));
}

// ----------------------------------------------------------------------------
// fp16 tiled layout (single source of truth):
//   [R rows][K cols] -> tiles 128 rows x 32 k-halfs (64 B/row, 8 KB/tile),
//   tile id = (row>>7)*KT + (col>>5).
//   Row layout: slot lc (16 B, lc=0..3) = halfs
//     [2lc, 2lc+1, 2lc+8, 2lc+9 | 16+2lc, 17+2lc, 24+2lc, 25+2lc]
//   -> one LDS.128 at (row, lc) yields the fragments for BOTH k16 steps.
//   Quarter-warp phases hit 8 distinct 16B slots -> conflict-free, pitch 64.
// ----------------------------------------------------------------------------
__device__ __forceinline__ size_t tiled16_byte(int row, int col) {
    int kt = col >> 5, c = col & 31;
    int ks = (c >> 4) & 1;
    int j  = c & 15;
    int lc = (j & 7) >> 1;
    int p  = ((j >> 3) << 1) | (c & 1);
    size_t tile = ((size_t)(row >> 7) * KT + kt) * (size_t)TILE16;
    return tile + (size_t)((row & 127) << 6) + lc * 16 + ks * 8 + p * 2;
}

// ============================================================================
// Pre-pass: fp32 row-major -> fp16 (RN) tiled scratch
// ============================================================================
__global__ void __launch_bounds__(256)
convert_tile16_kernel(const float* __restrict__ src, unsigned char* __restrict__ dst,
                      int R, int K)
{
    size_t gid = (size_t)blockIdx.x * 256 + threadIdx.x;
    size_t total = ((size_t)R * K) >> 2;
    if (gid >= total) return;
    int kq  = K >> 2;
    int row = (int)(gid / kq);
    int c4  = (int)(gid % kq) << 2;
    float4 v = *(const float4*)(src + (size_t)row * K + c4);
    __half2 h0 = __floats2half2_rn(v.x, v.y);
    __half2 h1 = __floats2half2_rn(v.z, v.w);
    *(__half2*)(dst + tiled16_byte(row, c4))     = h0;
    *(__half2*)(dst + tiled16_byte(row, c4 + 2)) = h1;
}

// ============================================================================
// GEMM: C[M,N] = At[M,K] @ Bt[N,K]^T + bias   (inputs pre-tiled fp16)
//   CTA 128x128, 8 warps (2x4) of 64x32 tiles, 3-stage cp.async.
//   NEW (R15): in-warp software pipeline — all B fragments loaded up front,
//   A fragments double-buffered so A[mt+1]'s 2 LDS.128 issue BEFORE the 8
//   MMAs of mt. The crossbar work slides under the tensor issue window by
//   scoreboard construction (independent of warp phasing), attacking the
//   measured 970(tensor)+1024(crossbar) serial sum.
// ============================================================================
static constexpr int STAGES = 3;
static constexpr int STAGE_BYTES = 2 * TILE16;          // A 8K + B 8K
static constexpr int GEMM_SMEM = STAGES * STAGE_BYTES;  // 48 KB

__global__ void __launch_bounds__(256, 2)
gemm_f16_kernel(const unsigned char* __restrict__ At, const unsigned char* __restrict__ Bt,
                const float* __restrict__ bias, float* __restrict__ C,
                int M, int N)
{
    extern __shared__ char smem[];
    uint32_t sb;
    asm("{ .reg .u64 t; cvta.to.shared.u64 t, %1; cvt.u32.u64 %0, t; }"
        : "=r"(sb) : "l"(smem));

    const int tid  = threadIdx.x;
    const int lane = tid & 31;
    const int w    = tid >> 5;
    const int wm   = w >> 2;     // 0..1  (64-row half)
    const int wn   = w & 3;      // 0..3  (32-col band)
    const int lg   = lane >> 2;  // 0..7
    const int lc   = lane & 3;   // 0..3

    // ---- grid swizzle: groups of 16 M-tiles, N-tile outer within group ----
    const int tiles_n = N >> 7;
    const int per = 16 * tiles_n;
    const int grp = blockIdx.x / per;
    const int r_  = blockIdx.x % per;
    const int mtile = grp * 16 + (r_ % 16);
    const int ntile = r_ / 16;
    const int m0 = mtile << 7, n0 = ntile << 7;

    // ---- producer: identity-copy one 8KB A tile + one 8KB B tile ----
    const unsigned char* Abase = At + (size_t)mtile * KT * TILE16;
    const unsigned char* Bbase = Bt + (size_t)ntile * KT * TILE16;
    const int o0 = tid * 16;
    const int o1 = (tid + 256) * 16;

    auto issue = [&](int kt, int s) {
        const unsigned char* asrc = Abase + (size_t)kt * TILE16;
        const unsigned char* bsrc = Bbase + (size_t)kt * TILE16;
        uint32_t ad = sb + s * STAGE_BYTES;
        uint32_t bd = ad + TILE16;
        asm volatile("cp.async.cg.shared.global [%0], [%1], 16;"
                     :: "r"(ad + o0), "l"(asrc + o0));
        asm volatile("cp.async.cg.shared.global [%0], [%1], 16;"
                     :: "r"(bd + o0), "l"(bsrc + o0));
        asm volatile("cp.async.cg.shared.global [%0], [%1], 16;"
                     :: "r"(ad + o1), "l"(asrc + o1));
        asm volatile("cp.async.cg.shared.global [%0], [%1], 16;"
                     :: "r"(bd + o1), "l"(bsrc + o1));
        asm volatile("cp.async.commit_group;" ::: "memory");
    };

    // ---- consumer addresses: row*64 + lc*16 ----
    uint32_t baseA[4], baseB[4];
#pragma unroll
    for (int mt = 0; mt < 4; ++mt)
        baseA[mt] = (uint32_t)((wm * 64 + mt * 16 + lg) << 6) + (uint32_t)(lc * 16);
#pragma unroll
    for (int nt = 0; nt < 4; ++nt)
        baseB[nt] = (uint32_t)TILE16 + (uint32_t)((wn * 32 + nt * 8 + lg) << 6)
                  + (uint32_t)(lc * 16);

    float acc[4][4][4];
#pragma unroll
    for (int mt = 0; mt < 4; ++mt)
#pragma unroll
        for (int nt = 0; nt < 4; ++nt)
#pragma unroll
            for (int i = 0; i < 4; ++i) acc[mt][nt][i] = 0.f;

    issue(0, 0);
    issue(1, 1);

#pragma unroll 1
    for (int kt = 0; kt < KT; ++kt) {
        const int s = kt % 3;
        if (kt + 1 < KT) asm volatile("cp.async.wait_group 1;" ::: "memory");
        else             asm volatile("cp.async.wait_group 0;" ::: "memory");
        __syncthreads();
        if (kt + 2 < KT) issue(kt + 2, (kt + 2) % 3);

        const uint32_t sg = sb + (uint32_t)(s * STAGE_BYTES);

        // ---- B fragments: all 4 up front (held for the whole kt) ----
        uint32_t bv[4][4];   // v0=b0(ks0) v1=b1(ks0) v2=b0(ks1) v3=b1(ks1)
#pragma unroll
        for (int nt = 0; nt < 4; ++nt) {
            uint32_t bd = sg + baseB[nt];
            asm("ld.shared.v4.b32 {%0,%1,%2,%3}, [%4];"
                : "=r"(bv[nt][0]), "=r"(bv[nt][1]),
                  "=r"(bv[nt][2]), "=r"(bv[nt][3]) : "r"(bd));
        }

        // ---- A fragments: double-buffered across mt ----
        // av[buf][h][0..3]: h=0 row lg, h=1 row lg+8;
        //   v0=a(ks0,lo) v1=a(ks0,hi) v2=a(ks1,lo) v3=a(ks1,hi)
        uint32_t av[2][2][4];
        {
            uint32_t ad = sg + baseA[0];
            asm("ld.shared.v4.b32 {%0,%1,%2,%3}, [%4];"
                : "=r"(av[0][0][0]), "=r"(av[0][0][1]),
                  "=r"(av[0][0][2]), "=r"(av[0][0][3]) : "r"(ad));
            asm("ld.shared.v4.b32 {%0,%1,%2,%3}, [%4+512];"
                : "=r"(av[0][1][0]), "=r"(av[0][1][1]),
                  "=r"(av[0][1][2]), "=r"(av[0][1][3]) : "r"(ad));
        }
#pragma unroll
        for (int mt = 0; mt < 4; ++mt) {
            const int cur = mt & 1;
            if (mt < 3) {   // prefetch A[mt+1] BEFORE this group's MMAs
                uint32_t ad = sg + baseA[mt + 1];
                asm("ld.shared.v4.b32 {%0,%1,%2,%3}, [%4];"
                    : "=r"(av[cur ^ 1][0][0]), "=r"(av[cur ^ 1][0][1]),
                      "=r"(av[cur ^ 1][0][2]), "=r"(av[cur ^ 1][0][3]) : "r"(ad));
                asm("ld.shared.v4.b32 {%0,%1,%2,%3}, [%4+512];"
                    : "=r"(av[cur ^ 1][1][0]), "=r"(av[cur ^ 1][1][1]),
                      "=r"(av[cur ^ 1][1][2]), "=r"(av[cur ^ 1][1][3]) : "r"(ad));
            }
#pragma unroll
            for (int nt = 0; nt < 4; ++nt) {
                // ks0
                mma_f16(acc[mt][nt][0], acc[mt][nt][1], acc[mt][nt][2], acc[mt][nt][3],
                        av[cur][0][0], av[cur][1][0], av[cur][0][1], av[cur][1][1],
                        bv[nt][0], bv[nt][1]);
                // ks1
                mma_f16(acc[mt][nt][0], acc[mt][nt][1], acc[mt][nt][2], acc[mt][nt][3],
                        av[cur][0][2], av[cur][1][2], av[cur][0][3], av[cur][1][3],
                        bv[nt][2], bv[nt][3]);
            }
        }
    }

    // ---- epilogue: direct float2 global stores with bias ----
#pragma unroll
    for (int nt = 0; nt < 4; ++nt) {
        const int col = n0 + wn * 32 + nt * 8 + 2 * lc;
        const float b0 = __ldg(bias + col), b1 = __ldg(bias + col + 1);
#pragma unroll
        for (int mt = 0; mt < 4; ++mt) {
            const int row = m0 + wm * 64 + mt * 16 + lg;
            float2 v0 = make_float2(acc[mt][nt][0] + b0, acc[mt][nt][1] + b1);
            float2 v1 = make_float2(acc[mt][nt][2] + b0, acc[mt][nt][3] + b1);
            *(float2*)(C + (size_t)row * N + col)       = v0;
            *(float2*)(C + (size_t)(row + 8) * N + col) = v1;
        }
    }
}

// ============================================================================
// Attention: per (b,h): s = q k^T * 0.125 + rel_bias[h]; p = softmax; o = p v
// qkv read fp32 (softmax inputs exact); output written fp16-tiled.
// ============================================================================
__global__ void __launch_bounds__(128)
attn_kernel(const float* __restrict__ qkv, const float* __restrict__ rel_bias,
            unsigned char* __restrict__ attn_ts)
{
    __shared__ float q[32][65], k[32][65], v[32][65], s[32][33];
    const int bh = blockIdx.x;
    const int b = bh >> 4, h = bh & 15;
    const int tid = threadIdx.x;

    const size_t base = (size_t)b * SEQ * NQKV + (size_t)h * HEAD_D;
    for (int i = tid; i < SEQ * HEAD_D; i += 128) {
        int n = i >> 6, d = i & 63;
        size_t a = base + (size_t)n * NQKV + d;
        q[n][d] = qkv[a];
        k[n][d] = qkv[a + 1024];
        v[n][d] = qkv[a + 2048];
    }
    __syncthreads();

    {
        const int n  = tid >> 2;
        const int mb = tid & 3;
        const float* rbp = rel_bias + ((size_t)h * 32 + n) * 32;
#pragma unroll
        for (int j = 0; j < 8; ++j) {
            int m = mb + 4 * j;
            float acc = 0.f;
#pragma unroll
            for (int d = 0; d < 64; ++d) acc += q[n][d] * k[m][d];
            s[n][m] = acc * 0.125f + rbp[m];
        }
    }
    __syncthreads();

    {
        const int lane = tid & 31, w = tid >> 5;
        for (int rr = w * 8; rr < w * 8 + 8; ++rr) {
            float x = s[rr][lane];
            float mx = x;
#pragma unroll
            for (int off = 16; off > 0; off >>= 1)
                mx = fmaxf(mx, __shfl_xor_sync(0xFFFFFFFFu, mx, off));
            float e = __expf(x - mx);
            float sum = e;
#pragma unroll
            for (int off = 16; off > 0; off >>= 1)
                sum += __shfl_xor_sync(0xFFFFFFFFu, sum, off);
            s[rr][lane] = e / sum;
        }
    }
    __syncthreads();

    // out = p @ v -> fp16 tiled (row = b*32+n, col = h*64+d), pairs of d
    for (int i = tid; i < SEQ * HEAD_D / 2; i += 128) {
        int n = i >> 5, d2 = (i & 31) << 1;
        float acc0 = 0.f, acc1 = 0.f;
#pragma unroll
        for (int m = 0; m < 32; ++m) {
            float p = s[n][m];
            acc0 += p * v[m][d2];
            acc1 += p * v[m][d2 + 1];
        }
        int row = b * SEQ + n;
        int col = h * HEAD_D + d2;
        *(__half2*)(attn_ts + tiled16_byte(row, col)) = __floats2half2_rn(acc0, acc1);
    }
}

// ============================================================================
// Launcher
// ============================================================================
extern "C" void kernel_launch(void* const* d_in, const int* in_sizes, int n_in,
                              void* d_out, int out_size)
{
    const float* x      = (const float*)d_in[0];
    const float* W_qkv  = (const float*)d_in[1];
    const float* b_qkv  = (const float*)d_in[2];
    const float* W_proj = (const float*)d_in[3];
    const float* b_proj = (const float*)d_in[4];
    const float* rbias  = (const float*)d_in[5];
    float* out = (float*)d_out;

    void *p_qkv = nullptr, *p_xs = nullptr, *p_at = nullptr,
         *p_wq = nullptr, *p_wp = nullptr;
    cudaGetSymbolAddress(&p_qkv, g_qkv);
    cudaGetSymbolAddress(&p_xs,  g_xs16);
    cudaGetSymbolAddress(&p_at,  g_at16);
    cudaGetSymbolAddress(&p_wq,  g_wq16);
    cudaGetSymbolAddress(&p_wp,  g_wp16);

    cudaFuncSetAttribute(gemm_f16_kernel,
                         cudaFuncAttributeMaxDynamicSharedMemorySize, GEMM_SMEM);

    // Pre-pass: convert + tile (x, W_qkv, W_proj) to fp16
    convert_tile16_kernel<<<((size_t)MDIM * KDIM / 4 + 255) / 256, 256>>>(
        x, (unsigned char*)p_xs, MDIM, KDIM);
    convert_tile16_kernel<<<((size_t)NQKV * KDIM / 4 + 255) / 256, 256>>>(
        W_qkv, (unsigned char*)p_wq, NQKV, KDIM);
    convert_tile16_kernel<<<((size_t)NPROJ * KDIM / 4 + 255) / 256, 256>>>(
        W_proj, (unsigned char*)p_wp, NPROJ, KDIM);

    // GEMM1: qkv = x @ W_qkv^T + b_qkv  [65536 x 3072] (fp32 out)
    gemm_f16_kernel<<<(MDIM / 128) * (NQKV / 128), 256, GEMM_SMEM>>>(
        (const unsigned char*)p_xs, (const unsigned char*)p_wq, b_qkv,
        (float*)p_qkv, MDIM, NQKV);

    // Attention: 2048*16 (b,h) blocks -> fp16 tiled scratch
    attn_kernel<<<BATCH * HEADS, 128>>>(
        (const float*)p_qkv, rbias, (unsigned char*)p_at);

    // GEMM2: out = attn @ W_proj^T + b_proj  [65536 x 1024]
    gemm_f16_kernel<<<(MDIM / 128) * (NPROJ / 128), 256, GEMM_SMEM>>>(
        (const unsigned char*)p_at, (const unsigned char*)p_wp, b_proj,
        out, MDIM, NPROJ);
}

// round 16
// speedup vs baseline: 3.0599x; 1.0882x over previous
#include <cuda_runtime.h>
#include <cuda_fp16.h>
#include <cstdint>

// ============================================================================
// Problem constants
// ============================================================================
#define MDIM   65536      // B*N = 2048*32
#define KDIM   1024       // model dim
#define NQKV   3072       // 3*DIM
#define NPROJ  1024
#define HEADS  16
#define HEAD_D 64
#define SEQ    32
#define BATCH  2048
#define KT     32         // k-tiles of 32 per K=1024

// fp16 tiled layout: tile = 128 rows x 32 k-halfs = 64 B/row, pitch 64, 8 KB
static constexpr int TILE16 = 8192;

// ============================================================================
// Scratch (allocation-free rule: __device__ globals)
// ============================================================================
__device__ __align__(256) __half g_qkv16[(size_t)MDIM * NQKV];           // 402 MB fp16
__device__ __align__(256) unsigned char g_xs16 [(size_t)(MDIM/128) * KT * TILE16]; // 134 MB
__device__ __align__(256) unsigned char g_at16 [(size_t)(MDIM/128) * KT * TILE16]; // 134 MB
__device__ __align__(256) unsigned char g_wq16 [(size_t)(NQKV/128) * KT * TILE16]; //   6 MB
__device__ __align__(256) unsigned char g_wp16 [(size_t)(NPROJ/128) * KT * TILE16];//   2 MB

// ============================================================================
// Helpers — BASELINE PTX ONLY (compute_103 target)
// ============================================================================

// m16n8k16 fp16 HMMA, fp32 accumulate
__device__ __forceinline__ void mma_f16(float& c0, float& c1, float& c2, float& c3,
                                        uint32_t a0, uint32_t a1, uint32_t a2, uint32_t a3,
                                        uint32_t b0, uint32_t b1) {
    asm volatile(
        "mma.sync.aligned.m16n8k16.row.col.f32.f16.f16.f32 "
        "{%0,%1,%2,%3}, {%4,%5,%6,%7}, {%8,%9}, {%0,%1,%2,%3};"
        : "+f"(c0), "+f"(c1), "+f"(c2), "+f"(c3)
        : "r"(a0), "r"(a1), "r"(a2), "r"(a3), "r"(b0), "r"(b1));
}

// ----------------------------------------------------------------------------
// fp16 tiled layout (single source of truth) — see R14/R15.
// One LDS.128 at (row, lc) yields the fragments for BOTH k16 steps;
// quarter-warp phases hit 8 distinct 16B slots -> conflict-free, pitch 64.
// ----------------------------------------------------------------------------
__device__ __forceinline__ size_t tiled16_byte(int row, int col) {
    int kt = col >> 5, c = col & 31;
    int ks = (c >> 4) & 1;
    int j  = c & 15;
    int lc = (j & 7) >> 1;
    int p  = ((j >> 3) << 1) | (c & 1);
    size_t tile = ((size_t)(row >> 7) * KT + kt) * (size_t)TILE16;
    return tile + (size_t)((row & 127) << 6) + lc * 16 + ks * 8 + p * 2;
}

// ============================================================================
// Pre-pass: fp32 row-major -> fp16 (RN) tiled scratch
// ============================================================================
__global__ void __launch_bounds__(256)
convert_tile16_kernel(const float* __restrict__ src, unsigned char* __restrict__ dst,
                      int R, int K)
{
    size_t gid = (size_t)blockIdx.x * 256 + threadIdx.x;
    size_t total = ((size_t)R * K) >> 2;
    if (gid >= total) return;
    int kq  = K >> 2;
    int row = (int)(gid / kq);
    int c4  = (int)(gid % kq) << 2;
    float4 v = *(const float4*)(src + (size_t)row * K + c4);
    __half2 h0 = __floats2half2_rn(v.x, v.y);
    __half2 h1 = __floats2half2_rn(v.z, v.w);
    *(__half2*)(dst + tiled16_byte(row, c4))     = h0;
    *(__half2*)(dst + tiled16_byte(row, c4 + 2)) = h1;
}

// ============================================================================
// GEMM: C[M,N] = At[M,K] @ Bt[N,K]^T + bias   (inputs pre-tiled fp16)
//   CTA 128x128, 8 warps (2x4) of 64x32 tiles.
//   R16: 6-stage cp.async (96 KB), ONE __syncthreads per kt-PAIR (16 total),
//   wait_group 2. Stage audit: pair p reads (2p)%6,(2p+1)%6, fills
//   (2p+4)%6,(2p+5)%6 = stages read in pair p-1 (protected by this sync).
//   In-warp pipeline per kt unchanged (B up front, A double-buffered).
//   HALF_OUT: GEMM1 stores qkv as fp16 (halves 1.2 GB of qkv traffic).
// ============================================================================
static constexpr int STAGES = 6;
static constexpr int STAGE_BYTES = 2 * TILE16;          // A 8K + B 8K
static constexpr int GEMM_SMEM = STAGES * STAGE_BYTES;  // 96 KB -> 2 CTAs/SM

template<bool HALF_OUT>
__global__ void __launch_bounds__(256, 2)
gemm_f16_kernel(const unsigned char* __restrict__ At, const unsigned char* __restrict__ Bt,
                const float* __restrict__ bias, void* __restrict__ Cv,
                int M, int N)
{
    extern __shared__ char smem[];
    uint32_t sb;
    asm("{ .reg .u64 t; cvta.to.shared.u64 t, %1; cvt.u32.u64 %0, t; }"
        : "=r"(sb) : "l"(smem));

    const int tid  = threadIdx.x;
    const int lane = tid & 31;
    const int w    = tid >> 5;
    const int wm   = w >> 2;     // 0..1  (64-row half)
    const int wn   = w & 3;      // 0..3  (32-col band)
    const int lg   = lane >> 2;  // 0..7
    const int lc   = lane & 3;   // 0..3

    // ---- grid swizzle: groups of 16 M-tiles, N-tile outer within group ----
    const int tiles_n = N >> 7;
    const int per = 16 * tiles_n;
    const int grp = blockIdx.x / per;
    const int r_  = blockIdx.x % per;
    const int mtile = grp * 16 + (r_ % 16);
    const int ntile = r_ / 16;
    const int m0 = mtile << 7, n0 = ntile << 7;

    // ---- producer ----
    const unsigned char* Abase = At + (size_t)mtile * KT * TILE16;
    const unsigned char* Bbase = Bt + (size_t)ntile * KT * TILE16;
    const int o0 = tid * 16;
    const int o1 = (tid + 256) * 16;

    auto issue = [&](int kt) {
        const int s = kt % STAGES;
        const unsigned char* asrc = Abase + (size_t)kt * TILE16;
        const unsigned char* bsrc = Bbase + (size_t)kt * TILE16;
        uint32_t ad = sb + s * STAGE_BYTES;
        uint32_t bd = ad + TILE16;
        asm volatile("cp.async.cg.shared.global [%0], [%1], 16;"
                     :: "r"(ad + o0), "l"(asrc + o0));
        asm volatile("cp.async.cg.shared.global [%0], [%1], 16;"
                     :: "r"(bd + o0), "l"(bsrc + o0));
        asm volatile("cp.async.cg.shared.global [%0], [%1], 16;"
                     :: "r"(ad + o1), "l"(asrc + o1));
        asm volatile("cp.async.cg.shared.global [%0], [%1], 16;"
                     :: "r"(bd + o1), "l"(bsrc + o1));
        asm volatile("cp.async.commit_group;" ::: "memory");
    };

    // ---- consumer addresses ----
    uint32_t baseA[4], baseB[4];
#pragma unroll
    for (int mt = 0; mt < 4; ++mt)
        baseA[mt] = (uint32_t)((wm * 64 + mt * 16 + lg) << 6) + (uint32_t)(lc * 16);
#pragma unroll
    for (int nt = 0; nt < 4; ++nt)
        baseB[nt] = (uint32_t)TILE16 + (uint32_t)((wn * 32 + nt * 8 + lg) << 6)
                  + (uint32_t)(lc * 16);

    float acc[4][4][4];
#pragma unroll
    for (int mt = 0; mt < 4; ++mt)
#pragma unroll
        for (int nt = 0; nt < 4; ++nt)
#pragma unroll
            for (int i = 0; i < 4; ++i) acc[mt][nt][i] = 0.f;

    // per-kt body: B fragments up front, A double-buffered across mt
    auto process = [&](int kt) {
        const uint32_t sg = sb + (uint32_t)((kt % STAGES) * STAGE_BYTES);
        uint32_t bv[4][4];
#pragma unroll
        for (int nt = 0; nt < 4; ++nt) {
            uint32_t bd = sg + baseB[nt];
            asm("ld.shared.v4.b32 {%0,%1,%2,%3}, [%4];"
                : "=r"(bv[nt][0]), "=r"(bv[nt][1]),
                  "=r"(bv[nt][2]), "=r"(bv[nt][3]) : "r"(bd));
        }
        uint32_t av[2][2][4];
        {
            uint32_t ad = sg + baseA[0];
            asm("ld.shared.v4.b32 {%0,%1,%2,%3}, [%4];"
                : "=r"(av[0][0][0]), "=r"(av[0][0][1]),
                  "=r"(av[0][0][2]), "=r"(av[0][0][3]) : "r"(ad));
            asm("ld.shared.v4.b32 {%0,%1,%2,%3}, [%4+512];"
                : "=r"(av[0][1][0]), "=r"(av[0][1][1]),
                  "=r"(av[0][1][2]), "=r"(av[0][1][3]) : "r"(ad));
        }
#pragma unroll
        for (int mt = 0; mt < 4; ++mt) {
            const int cur = mt & 1;
            if (mt < 3) {
                uint32_t ad = sg + baseA[mt + 1];
                asm("ld.shared.v4.b32 {%0,%1,%2,%3}, [%4];"
                    : "=r"(av[cur ^ 1][0][0]), "=r"(av[cur ^ 1][0][1]),
                      "=r"(av[cur ^ 1][0][2]), "=r"(av[cur ^ 1][0][3]) : "r"(ad));
                asm("ld.shared.v4.b32 {%0,%1,%2,%3}, [%4+512];"
                    : "=r"(av[cur ^ 1][1][0]), "=r"(av[cur ^ 1][1][1]),
                      "=r"(av[cur ^ 1][1][2]), "=r"(av[cur ^ 1][1][3]) : "r"(ad));
            }
#pragma unroll
            for (int nt = 0; nt < 4; ++nt) {
                mma_f16(acc[mt][nt][0], acc[mt][nt][1], acc[mt][nt][2], acc[mt][nt][3],
                        av[cur][0][0], av[cur][1][0], av[cur][0][1], av[cur][1][1],
                        bv[nt][0], bv[nt][1]);
                mma_f16(acc[mt][nt][0], acc[mt][nt][1], acc[mt][nt][2], acc[mt][nt][3],
                        av[cur][0][2], av[cur][1][2], av[cur][0][3], av[cur][1][3],
                        bv[nt][2], bv[nt][3]);
            }
        }
    };

    issue(0); issue(1); issue(2); issue(3);

#pragma unroll 1
    for (int p = 0; p < KT / 2; ++p) {
        const int k0 = 2 * p;
        asm volatile("cp.async.wait_group 2;" ::: "memory");
        __syncthreads();
        if (k0 + 4 < KT) issue(k0 + 4);
        if (k0 + 5 < KT) issue(k0 + 5);
        process(k0);
        process(k0 + 1);
    }

    // ---- epilogue ----
#pragma unroll
    for (int nt = 0; nt < 4; ++nt) {
        const int col = n0 + wn * 32 + nt * 8 + 2 * lc;
        const float b0 = __ldg(bias + col), b1 = __ldg(bias + col + 1);
#pragma unroll
        for (int mt = 0; mt < 4; ++mt) {
            const int row = m0 + wm * 64 + mt * 16 + lg;
            if (HALF_OUT) {
                __half* C16 = (__half*)Cv;
                *(__half2*)(C16 + (size_t)row * N + col) =
                    __floats2half2_rn(acc[mt][nt][0] + b0, acc[mt][nt][1] + b1);
                *(__half2*)(C16 + (size_t)(row + 8) * N + col) =
                    __floats2half2_rn(acc[mt][nt][2] + b0, acc[mt][nt][3] + b1);
            } else {
                float* C = (float*)Cv;
                *(float2*)(C + (size_t)row * N + col) =
                    make_float2(acc[mt][nt][0] + b0, acc[mt][nt][1] + b1);
                *(float2*)(C + (size_t)(row + 8) * N + col) =
                    make_float2(acc[mt][nt][2] + b0, acc[mt][nt][3] + b1);
            }
        }
    }
}

// ============================================================================
// Attention: per (b,h): s = q k^T * 0.125 + rel_bias[h]; p = softmax; o = p v
// qkv read fp16 (halved traffic), math fp32, output fp16-tiled.
// ============================================================================
__global__ void __launch_bounds__(128)
attn_kernel(const __half* __restrict__ qkv, const float* __restrict__ rel_bias,
            unsigned char* __restrict__ attn_ts)
{
    __shared__ float q[32][65], k[32][65], v[32][65], s[32][33];
    const int bh = blockIdx.x;
    const int b = bh >> 4, h = bh & 15;
    const int tid = threadIdx.x;

    const size_t base = (size_t)b * SEQ * NQKV + (size_t)h * HEAD_D;
    for (int i = tid; i < SEQ * HEAD_D / 2; i += 128) {
        int n = i >> 5, d2 = (i & 31) << 1;
        size_t a = base + (size_t)n * NQKV + d2;
        float2 fq = __half22float2(*(const __half2*)(qkv + a));
        float2 fk = __half22float2(*(const __half2*)(qkv + a + 1024));
        float2 fv = __half22float2(*(const __half2*)(qkv + a + 2048));
        q[n][d2] = fq.x; q[n][d2 + 1] = fq.y;
        k[n][d2] = fk.x; k[n][d2 + 1] = fk.y;
        v[n][d2] = fv.x; v[n][d2 + 1] = fv.y;
    }
    __syncthreads();

    {
        const int n  = tid >> 2;
        const int mb = tid & 3;
        const float* rbp = rel_bias + ((size_t)h * 32 + n) * 32;
#pragma unroll
        for (int j = 0; j < 8; ++j) {
            int m = mb + 4 * j;
            float acc = 0.f;
#pragma unroll
            for (int d = 0; d < 64; ++d) acc += q[n][d] * k[m][d];
            s[n][m] = acc * 0.125f + rbp[m];
        }
    }
    __syncthreads();

    {
        const int lane = tid & 31, w = tid >> 5;
        for (int rr = w * 8; rr < w * 8 + 8; ++rr) {
            float x = s[rr][lane];
            float mx = x;
#pragma unroll
            for (int off = 16; off > 0; off >>= 1)
                mx = fmaxf(mx, __shfl_xor_sync(0xFFFFFFFFu, mx, off));
            float e = __expf(x - mx);
            float sum = e;
#pragma unroll
            for (int off = 16; off > 0; off >>= 1)
                sum += __shfl_xor_sync(0xFFFFFFFFu, sum, off);
            s[rr][lane] = e / sum;
        }
    }
    __syncthreads();

    // out = p @ v -> fp16 tiled (row = b*32+n, col = h*64+d), pairs of d
    for (int i = tid; i < SEQ * HEAD_D / 2; i += 128) {
        int n = i >> 5, d2 = (i & 31) << 1;
        float acc0 = 0.f, acc1 = 0.f;
#pragma unroll
        for (int m = 0; m < 32; ++m) {
            float p = s[n][m];
            acc0 += p * v[m][d2];
            acc1 += p * v[m][d2 + 1];
        }
        int row = b * SEQ + n;
        int col = h * HEAD_D + d2;
        *(__half2*)(attn_ts + tiled16_byte(row, col)) = __floats2half2_rn(acc0, acc1);
    }
}

// ============================================================================
// Launcher
// ============================================================================
extern "C" void kernel_launch(void* const* d_in, const int* in_sizes, int n_in,
                              void* d_out, int out_size)
{
    const float* x      = (const float*)d_in[0];
    const float* W_qkv  = (const float*)d_in[1];
    const float* b_qkv  = (const float*)d_in[2];
    const float* W_proj = (const float*)d_in[3];
    const float* b_proj = (const float*)d_in[4];
    const float* rbias  = (const float*)d_in[5];
    float* out = (float*)d_out;

    void *p_qkv = nullptr, *p_xs = nullptr, *p_at = nullptr,
         *p_wq = nullptr, *p_wp = nullptr;
    cudaGetSymbolAddress(&p_qkv, g_qkv16);
    cudaGetSymbolAddress(&p_xs,  g_xs16);
    cudaGetSymbolAddress(&p_at,  g_at16);
    cudaGetSymbolAddress(&p_wq,  g_wq16);
    cudaGetSymbolAddress(&p_wp,  g_wp16);

    cudaFuncSetAttribute(gemm_f16_kernel<true>,
                         cudaFuncAttributeMaxDynamicSharedMemorySize, GEMM_SMEM);
    cudaFuncSetAttribute(gemm_f16_kernel<false>,
                         cudaFuncAttributeMaxDynamicSharedMemorySize, GEMM_SMEM);

    // Pre-pass: convert + tile (x, W_qkv, W_proj) to fp16
    convert_tile16_kernel<<<((size_t)MDIM * KDIM / 4 + 255) / 256, 256>>>(
        x, (unsigned char*)p_xs, MDIM, KDIM);
    convert_tile16_kernel<<<((size_t)NQKV * KDIM / 4 + 255) / 256, 256>>>(
        W_qkv, (unsigned char*)p_wq, NQKV, KDIM);
    convert_tile16_kernel<<<((size_t)NPROJ * KDIM / 4 + 255) / 256, 256>>>(
        W_proj, (unsigned char*)p_wp, NPROJ, KDIM);

    // GEMM1: qkv = x @ W_qkv^T + b_qkv  [65536 x 3072] -> fp16 out
    gemm_f16_kernel<true><<<(MDIM / 128) * (NQKV / 128), 256, GEMM_SMEM>>>(
        (const unsigned char*)p_xs, (const unsigned char*)p_wq, b_qkv,
        p_qkv, MDIM, NQKV);

    // Attention: 2048*16 (b,h) blocks -> fp16 tiled scratch
    attn_kernel<<<BATCH * HEADS, 128>>>(
        (const __half*)p_qkv, rbias, (unsigned char*)p_at);

    // GEMM2: out = attn @ W_proj^T + b_proj  [65536 x 1024] -> fp32 out
    gemm_f16_kernel<false><<<(MDIM / 128) * (NPROJ / 128), 256, GEMM_SMEM>>>(
        (const unsigned char*)p_at, (const unsigned char*)p_wp, b_proj,
        d_out, MDIM, NPROJ);
}